// round 6
// baseline (speedup 1.0000x reference)
#include <cuda_runtime.h>
#include <math.h>

// Problem constants
#define BATCH   4096
#define VOCABSZ 100000
#define EMBDIM  64
#define D_IN    256
#define D_H     256
#define D_OUT   128
#define N_NEG4  4

// Scratch: NORMALIZED tower outputs (u then v), 2 * 4096 * 128 floats = 4 MB
__device__ float g_uv[2u * BATCH * D_OUT];

// Tiling
constexpr int TM   = 64;     // rows per block
constexpr int STR2 = 132;    // floats per k-slot: 2*64 duplicated + 4 pad
constexpr int XS_FLOATS   = 256 * STR2;          // 33792 floats = 135168 B
constexpr int WBUF_FLOATS = 32 * 256;            // one W tile buffer (8192 floats)
constexpr int SMEM_FLOATS = XS_FLOATS + 2 * WBUF_FLOATS;   // 200704 B total

// Packed fp32 FMA2 (sm_100+): two MACs per instruction
#define FMA2(acc, a, b) \
    asm("fma.rn.f32x2 %0, %1, %2, %0;" : "+l"(acc) : "l"(a), "l"(b))

__device__ __forceinline__ void cp16(float* s, const float* g) {
    unsigned saddr = (unsigned)__cvta_generic_to_shared(s);
    asm volatile("cp.async.cg.shared.global [%0], [%1], 16;" :: "r"(saddr), "l"(g));
}
#define CP_COMMIT()  asm volatile("cp.async.commit_group;" ::: "memory")
#define CP_WAIT_ALL() asm volatile("cp.async.wait_group 0;" ::: "memory")

__global__ __launch_bounds__(512, 1)
void tower_kernel(const int* __restrict__ user_ids, const int* __restrict__ item_ids,
                  const float* __restrict__ user_tables, const float* __restrict__ item_tables,
                  const float* __restrict__ uW1, const float* __restrict__ ub1,
                  const float* __restrict__ uW2, const float* __restrict__ ub2,
                  const float* __restrict__ iW1, const float* __restrict__ ib1,
                  const float* __restrict__ iW2, const float* __restrict__ ib2)
{
    extern __shared__ float smem[];
    float* Xs = smem;                 // duplicated [256][STR2]: Xs[k][2r]=Xs[k][2r+1]=X[r][k]
    float* Wb0 = smem + XS_FLOATS;    // W tile double buffers
    float* Wb1 = Wb0 + WBUF_FLOATS;

    const int tower  = blockIdx.x >> 6;
    const int rowblk = blockIdx.x & 63;

    const int*   ids = tower ? item_ids    : user_ids;
    const float* tbl = tower ? item_tables : user_tables;
    const float* W1  = tower ? iW1 : uW1;
    const float* b1  = tower ? ib1 : ub1;
    const float* W2  = tower ? iW2 : uW2;
    const float* b2  = tower ? ib2 : ub2;
    float* gout = g_uv + (size_t)tower * BATCH * D_OUT;

    const int tid  = threadIdx.x;     // 512 threads
    const int x    = tid & 15;        // column-pair group
    const int y    = tid >> 4;        // 32 row groups of 2 rows
    const int row0 = rowblk * TM;

    // ---- Prologue: kick off W1 tile 0 load, then gather embeddings ----
    #pragma unroll
    for (int i = tid; i < 2048; i += 512) {          // 32x256 floats, 16B chunks
        int kr = i >> 6, nc = (i & 63) << 2;
        cp16(&Wb0[kr * 256 + nc], &W1[kr * 256 + nc]);
    }
    CP_COMMIT();

    // Embedding gather (duplicated, transposed). Thread owns column c, half rows.
    {
        const int c    = tid & 255;
        const int half = tid >> 8;                   // 0 or 1
        const int f = c >> 6, e = c & 63;
        const float* tf = tbl + (size_t)f * VOCABSZ * EMBDIM + e;
        const int* idp = ids + f;
        float* xc = &Xs[c * STR2 + half * 64];
        const int rbase = row0 + half * 32;
        #pragma unroll 4
        for (int r = 0; r < 32; ++r) {
            int id  = __ldg(&idp[(rbase + r) * 4]);
            float v = __ldg(&tf[(size_t)id * EMBDIM]);
            *(float2*)&xc[2 * r] = make_float2(v, v);
        }
    }

    // ---------------- GEMM1: H[64,256] = relu(X @ W1 + b1) ----------------
    unsigned long long acc[2][8] = {};   // acc[p][j] = row(2y+p) x cols(2x+32j, +1)

    #pragma unroll 1
    for (int t = 0; t < 8; ++t) {
        CP_WAIT_ALL();                   // tile t resident in buf[t&1]
        __syncthreads();                 // everyone past compute(t-1)
        if (t < 7) {                     // prefetch tile t+1 into other buffer
            float* wn = (t & 1) ? Wb0 : Wb1;
            const float* gsrc = W1 + (t + 1) * 32 * 256;
            #pragma unroll
            for (int i = tid; i < 2048; i += 512) {
                int kr = i >> 6, nc = (i & 63) << 2;
                cp16(&wn[kr * 256 + nc], &gsrc[kr * 256 + nc]);
            }
            CP_COMMIT();
        }
        const float* ws = (t & 1) ? Wb1 : Wb0;
        const int kt = t * 32;
        #pragma unroll 8
        for (int k = 0; k < 32; ++k) {
            ulonglong2 xa = *(const ulonglong2*)&Xs[(kt + k) * STR2 + 4 * y];
            #pragma unroll
            for (int j = 0; j < 8; ++j) {
                unsigned long long w =
                    *(const unsigned long long*)&ws[k * 256 + 2 * x + 32 * j];
                FMA2(acc[0][j], xa.x, w);
                FMA2(acc[1][j], xa.y, w);
            }
        }
    }

    // Kick off W2 tile 0 into Wb0 (last used at t=6; all threads past t=6's sync)
    #pragma unroll
    for (int i = tid; i < 1024; i += 512) {          // 32x128 floats
        int kr = i >> 5, nc = (i & 31) << 2;
        cp16(&Wb0[kr * 128 + nc], &W2[kr * 128 + nc]);
    }
    CP_COMMIT();
    __syncthreads();                     // all compute(t=7) done before Xs overwrite

    // bias + relu, write H duplicated back into Xs
    #pragma unroll
    for (int j = 0; j < 8; ++j) {
        int c0 = 2 * x + 32 * j;
        float2 bb = *(const float2*)&b1[c0];
        #pragma unroll
        for (int p = 0; p < 2; ++p) {
            float2 s = *reinterpret_cast<float2*>(&acc[p][j]);
            float h0 = fmaxf(s.x + bb.x, 0.f);
            float h1 = fmaxf(s.y + bb.y, 0.f);
            int r = 2 * y + p;
            *(float2*)&Xs[(size_t)c0 * STR2 + 2 * r]       = make_float2(h0, h0);
            *(float2*)&Xs[(size_t)(c0 + 1) * STR2 + 2 * r] = make_float2(h1, h1);
        }
    }

    // ---------------- GEMM2: U[64,128] = relu(H @ W2 + b2) ----------------
    unsigned long long acc2[2][4] = {};

    #pragma unroll 1
    for (int t = 0; t < 8; ++t) {
        CP_WAIT_ALL();
        __syncthreads();                 // also orders the H write-back for t=0
        if (t < 7) {
            float* wn = (t & 1) ? Wb0 : Wb1;
            const float* gsrc = W2 + (t + 1) * 32 * 128;
            #pragma unroll
            for (int i = tid; i < 1024; i += 512) {
                int kr = i >> 5, nc = (i & 31) << 2;
                cp16(&wn[kr * 128 + nc], &gsrc[kr * 128 + nc]);
            }
            CP_COMMIT();
        }
        const float* ws = (t & 1) ? Wb1 : Wb0;
        const int kt = t * 32;
        #pragma unroll 8
        for (int k = 0; k < 32; ++k) {
            ulonglong2 xa = *(const ulonglong2*)&Xs[(kt + k) * STR2 + 4 * y];
            #pragma unroll
            for (int j = 0; j < 4; ++j) {
                unsigned long long w =
                    *(const unsigned long long*)&ws[k * 128 + 2 * x + 32 * j];
                FMA2(acc2[0][j], xa.x, w);
                FMA2(acc2[1][j], xa.y, w);
            }
        }
    }

    // ---------------- Epilogue: bias + relu + row-normalize + store ----------------
    float h[2][8];
    float sq[2] = {0.f, 0.f};
    #pragma unroll
    for (int j = 0; j < 4; ++j) {
        int c0 = 2 * x + 32 * j;
        float2 bb = *(const float2*)&b2[c0];
        #pragma unroll
        for (int p = 0; p < 2; ++p) {
            float2 s = *reinterpret_cast<float2*>(&acc2[p][j]);
            float h0 = fmaxf(s.x + bb.x, 0.f);
            float h1 = fmaxf(s.y + bb.y, 0.f);
            h[p][2 * j]     = h0;
            h[p][2 * j + 1] = h1;
            sq[p] = fmaf(h0, h0, fmaf(h1, h1, sq[p]));
        }
    }
    // reduce squared norms across the 16 x-lanes (bit4 of lane = y parity, untouched)
    #pragma unroll
    for (int o = 8; o; o >>= 1) {
        sq[0] += __shfl_xor_sync(0xffffffffu, sq[0], o);
        sq[1] += __shfl_xor_sync(0xffffffffu, sq[1], o);
    }
    float inv[2];
    inv[0] = 1.f / fmaxf(sqrtf(sq[0]), 1e-8f);
    inv[1] = 1.f / fmaxf(sqrtf(sq[1]), 1e-8f);

    #pragma unroll
    for (int j = 0; j < 4; ++j) {
        int c0 = 2 * x + 32 * j;
        #pragma unroll
        for (int p = 0; p < 2; ++p) {
            int r = row0 + 2 * y + p;
            *(float2*)&gout[(size_t)r * D_OUT + c0] =
                make_float2(h[p][2 * j] * inv[p], h[p][2 * j + 1] * inv[p]);
        }
    }
}

// ---------------- Scoring on pre-normalized vectors ----------------
__global__ __launch_bounds__(256)
void score_kernel(const int* __restrict__ sw_ids, const float* __restrict__ sw_table,
                  float* __restrict__ out)
{
    int warp = (blockIdx.x * blockDim.x + threadIdx.x) >> 5;
    if (warp >= BATCH) return;
    int lane = threadIdx.x & 31;
    int g    = lane >> 3;      // which band column
    int l8   = lane & 7;

    const float* un = g_uv;
    const float* vn = g_uv + (size_t)BATCH * D_OUT;

    int col = (warp + g) & (BATCH - 1);
    const float4* u4 = (const float4*)&un[(size_t)warp * D_OUT + l8 * 16];
    const float4* v4 = (const float4*)&vn[(size_t)col  * D_OUT + l8 * 16];

    float d = 0.f;
    #pragma unroll
    for (int i = 0; i < 4; ++i) {
        float4 a = u4[i], b = v4[i];
        d = fmaf(a.x, b.x, fmaf(a.y, b.y, fmaf(a.z, b.z, fmaf(a.w, b.w, d))));
    }
    d += __shfl_xor_sync(0xffffffffu, d, 4);
    d += __shfl_xor_sync(0xffffffffu, d, 2);
    d += __shfl_xor_sync(0xffffffffu, d, 1);

    if (l8 == 0)
        out[warp * N_NEG4 + g] =
            d - logf(__ldg(&sw_table[__ldg(&sw_ids[col])]));
}

extern "C" void kernel_launch(void* const* d_in, const int* in_sizes, int n_in,
                              void* d_out, int out_size)
{
    const int*   user_ids    = (const int*)  d_in[0];
    const int*   item_ids    = (const int*)  d_in[1];
    const int*   sw_ids      = (const int*)  d_in[2];
    const float* user_tables = (const float*)d_in[3];
    const float* item_tables = (const float*)d_in[4];
    const float* sw_table    = (const float*)d_in[5];
    const float* uW1 = (const float*)d_in[6];
    const float* ub1 = (const float*)d_in[7];
    const float* uW2 = (const float*)d_in[8];
    const float* ub2 = (const float*)d_in[9];
    const float* iW1 = (const float*)d_in[10];
    const float* ib1 = (const float*)d_in[11];
    const float* iW2 = (const float*)d_in[12];
    const float* ib2 = (const float*)d_in[13];
    (void)in_sizes; (void)n_in; (void)out_size;

    const int smem_bytes = SMEM_FLOATS * (int)sizeof(float);   // 200,704 B
    cudaFuncSetAttribute(tower_kernel, cudaFuncAttributeMaxDynamicSharedMemorySize,
                         smem_bytes);

    tower_kernel<<<128, 512, smem_bytes>>>(user_ids, item_ids,
                                           user_tables, item_tables,
                                           uW1, ub1, uW2, ub2,
                                           iW1, ib1, iW2, ib2);
    score_kernel<<<512, 256>>>(sw_ids, sw_table, (float*)d_out);
}

// round 7
// speedup vs baseline: 2.3881x; 2.3881x over previous
#include <cuda_runtime.h>
#include <math.h>

// Problem constants
#define BATCH   4096
#define VOCABSZ 100000
#define EMBDIM  64
#define D_IN    256
#define D_H     256
#define D_OUT   128
#define N_NEG4  4

// Scratch: NORMALIZED tower outputs (u then v)
__device__ float g_uv[2u * BATCH * D_OUT];

// Tiling
constexpr int TM    = 64;    // rows per block
constexpr int XSTR  = 260;   // X/H smem row stride (floats): (4g+t)%32 distinct -> conflict-free
constexpr int W1STR = 264;   // W1 tile stride: bank (8t+g)%32 distinct
constexpr int W2STR = 136;   // W2 tile stride
constexpr int USTR  = 129;   // U staging stride: bank r%32 -> broadcast-clean
constexpr int XS_FLOATS   = TM * XSTR;            // 16640
constexpr int WBUF_FLOATS = 32 * W1STR;           // 8448 (max of W1 tile, W2 tile 4352, U 8256)
constexpr int SMEM_FLOATS = XS_FLOATS + 2 * WBUF_FLOATS;   // 33536 floats = 134144 B

__device__ __forceinline__ unsigned f2tf32(float f) {
    unsigned r; asm("cvt.rna.tf32.f32 %0, %1;" : "=r"(r) : "f"(f)); return r;
}
__device__ __forceinline__ float tf32f(float f) { return __uint_as_float(f2tf32(f)); }

#define MMA_TF32(c, a, b0, b1)                                              \
    asm volatile("mma.sync.aligned.m16n8k8.row.col.f32.tf32.tf32.f32 "      \
        "{%0,%1,%2,%3}, {%4,%5,%6,%7}, {%8,%9}, {%0,%1,%2,%3};"             \
        : "+f"((c)[0]), "+f"((c)[1]), "+f"((c)[2]), "+f"((c)[3])            \
        : "r"((a)[0]), "r"((a)[1]), "r"((a)[2]), "r"((a)[3]),               \
          "r"(b0), "r"(b1))

__device__ __forceinline__ void cp16(float* s, const float* g) {
    unsigned saddr = (unsigned)__cvta_generic_to_shared(s);
    asm volatile("cp.async.cg.shared.global [%0], [%1], 16;" :: "r"(saddr), "l"(g));
}
#define CP_COMMIT()   asm volatile("cp.async.commit_group;" ::: "memory")
#define CP_WAIT_ALL() asm volatile("cp.async.wait_group 0;" ::: "memory")

__global__ __launch_bounds__(256, 1)
void tower_kernel(const int* __restrict__ user_ids, const int* __restrict__ item_ids,
                  const float* __restrict__ user_tables, const float* __restrict__ item_tables,
                  const float* __restrict__ uW1, const float* __restrict__ ub1,
                  const float* __restrict__ uW2, const float* __restrict__ ub2,
                  const float* __restrict__ iW1, const float* __restrict__ ib1,
                  const float* __restrict__ iW2, const float* __restrict__ ib2)
{
    extern __shared__ float smem[];
    float* Xs  = smem;                 // X then H, [64][XSTR], tf32 bit patterns
    float* Wb0 = smem + XS_FLOATS;     // W tile double buffers / U staging
    float* Wb1 = Wb0 + WBUF_FLOATS;

    const int tower  = blockIdx.x >> 6;
    const int rowblk = blockIdx.x & 63;

    const int*   ids = tower ? item_ids    : user_ids;
    const float* tbl = tower ? item_tables : user_tables;
    const float* W1  = tower ? iW1 : uW1;
    const float* b1  = tower ? ib1 : ub1;
    const float* W2  = tower ? iW2 : uW2;
    const float* b2  = tower ? ib2 : ub2;
    float* gout = g_uv + (size_t)tower * BATCH * D_OUT;

    const int tid  = threadIdx.x;      // 256 threads = 8 warps
    const int warp = tid >> 5;
    const int lane = tid & 31;
    const int g    = lane >> 2;        // 0..7
    const int t4   = lane & 3;         // 0..3
    const int row0 = rowblk * TM;

    // ---- Prologue: launch W1 tile 0 (32x256) into Wb0 ----
    #pragma unroll
    for (int i = tid; i < 32 * 64; i += 256) {
        int kr = i >> 6, f4 = (i & 63) << 2;
        cp16(&Wb0[kr * W1STR + f4], &W1[kr * 256 + f4]);
    }
    CP_COMMIT();

    // ---- Embedding gather: X[r][c] (tf32-rounded) ----
    {
        const int f = tid >> 6, e = tid & 63;          // column c = tid
        const float* tf = tbl + (size_t)f * VOCABSZ * EMBDIM + e;
        const int* idp = ids + f;
        #pragma unroll 4
        for (int r = 0; r < TM; ++r) {
            int id = __ldg(&idp[(row0 + r) * 4]);
            Xs[r * XSTR + tid] = tf32f(__ldg(&tf[(size_t)id * EMBDIM]));
        }
    }

    // ================ GEMM1: H[64,256] = relu(X @ W1 + b1) ================
    // Warp tile: 64m x 32n (4 m16-tiles x 4 n8-tiles), n0 = warp*32
    const int n0 = warp * 32;
    float c1[4][4][4];
    #pragma unroll
    for (int mt = 0; mt < 4; ++mt)
        #pragma unroll
        for (int u = 0; u < 4; ++u)
            #pragma unroll
            for (int i = 0; i < 4; ++i) c1[mt][u][i] = 0.f;

    #pragma unroll 1
    for (int tt = 0; tt < 8; ++tt) {
        CP_WAIT_ALL();
        __syncthreads();
        if (tt < 7) {
            float* wn = (tt & 1) ? Wb0 : Wb1;
            const float* gsrc = W1 + (tt + 1) * 32 * 256;
            #pragma unroll
            for (int i = tid; i < 32 * 64; i += 256) {
                int kr = i >> 6, f4 = (i & 63) << 2;
                cp16(&wn[kr * W1STR + f4], &gsrc[kr * 256 + f4]);
            }
            CP_COMMIT();
        }
        const float* ws = (tt & 1) ? Wb1 : Wb0;
        #pragma unroll
        for (int ks = 0; ks < 4; ++ks) {               // k8-steps within tile
            const int kk = tt * 32 + ks * 8;
            unsigned a[4][4];
            #pragma unroll
            for (int mt = 0; mt < 4; ++mt) {
                const float* xr = Xs + (mt * 16 + g) * XSTR + kk + t4;
                a[mt][0] = __float_as_uint(xr[0]);
                a[mt][1] = __float_as_uint(xr[8 * XSTR]);
                a[mt][2] = __float_as_uint(xr[4]);
                a[mt][3] = __float_as_uint(xr[8 * XSTR + 4]);
            }
            const float* wk = ws + (ks * 8 + t4) * W1STR + n0 + g;
            #pragma unroll
            for (int u = 0; u < 4; ++u) {
                unsigned b0 = f2tf32(wk[8 * u]);
                unsigned b1r = f2tf32(wk[4 * W1STR + 8 * u]);
                #pragma unroll
                for (int mt = 0; mt < 4; ++mt)
                    MMA_TF32(c1[mt][u], a[mt], b0, b1r);
            }
        }
    }

    // Launch W2 tile 0 (32x128) into Wb0 (free: last read was GEMM1 tile 6)
    #pragma unroll
    for (int i = tid; i < 32 * 32; i += 256) {
        int kr = i >> 5, f4 = (i & 31) << 2;
        cp16(&Wb0[kr * W2STR + f4], &W2[kr * 256 * 0 + kr * 0 + (kr * 128) + f4 - kr * 128 + kr * 128]);
    }
    CP_COMMIT();
    __syncthreads();       // everyone done reading X before overwrite

    // bias + relu, H (tf32) back into Xs
    #pragma unroll
    for (int u = 0; u < 4; ++u) {
        int col0 = n0 + 8 * u + 2 * t4;
        float2 bb = *(const float2*)&b1[col0];
        #pragma unroll
        for (int mt = 0; mt < 4; ++mt) {
            int r = mt * 16 + g;
            float2 h0, h1;
            h0.x = tf32f(fmaxf(c1[mt][u][0] + bb.x, 0.f));
            h0.y = tf32f(fmaxf(c1[mt][u][1] + bb.y, 0.f));
            h1.x = tf32f(fmaxf(c1[mt][u][2] + bb.x, 0.f));
            h1.y = tf32f(fmaxf(c1[mt][u][3] + bb.y, 0.f));
            *(float2*)&Xs[r * XSTR + col0]       = h0;
            *(float2*)&Xs[(r + 8) * XSTR + col0] = h1;
        }
    }

    // ================ GEMM2: U[64,128] = relu(H @ W2 + b2) ================
    // Warp tile: 64m x 16n, n0_2 = warp*16
    const int n02 = warp * 16;
    float c2[4][2][4];
    #pragma unroll
    for (int mt = 0; mt < 4; ++mt)
        #pragma unroll
        for (int u = 0; u < 2; ++u)
            #pragma unroll
            for (int i = 0; i < 4; ++i) c2[mt][u][i] = 0.f;

    #pragma unroll 1
    for (int tt = 0; tt < 8; ++tt) {
        CP_WAIT_ALL();
        __syncthreads();               // also orders H writes at tt=0
        if (tt < 7) {
            float* wn = (tt & 1) ? Wb0 : Wb1;
            const float* gsrc = W2 + (tt + 1) * 32 * 128;
            #pragma unroll
            for (int i = tid; i < 32 * 32; i += 256) {
                int kr = i >> 5, f4 = (i & 31) << 2;
                cp16(&wn[kr * W2STR + f4], &gsrc[kr * 128 + f4]);
            }
            CP_COMMIT();
        }
        const float* ws = (tt & 1) ? Wb1 : Wb0;
        #pragma unroll
        for (int ks = 0; ks < 4; ++ks) {
            const int kk = tt * 32 + ks * 8;
            unsigned a[4][4];
            #pragma unroll
            for (int mt = 0; mt < 4; ++mt) {
                const float* xr = Xs + (mt * 16 + g) * XSTR + kk + t4;
                a[mt][0] = __float_as_uint(xr[0]);
                a[mt][1] = __float_as_uint(xr[8 * XSTR]);
                a[mt][2] = __float_as_uint(xr[4]);
                a[mt][3] = __float_as_uint(xr[8 * XSTR + 4]);
            }
            const float* wk = ws + (ks * 8 + t4) * W2STR + n02 + g;
            #pragma unroll
            for (int u = 0; u < 2; ++u) {
                unsigned b0 = f2tf32(wk[8 * u]);
                unsigned b1r = f2tf32(wk[4 * W2STR + 8 * u]);
                #pragma unroll
                for (int mt = 0; mt < 4; ++mt)
                    MMA_TF32(c2[mt][u], a[mt], b0, b1r);
            }
        }
    }

    // ---- Epilogue: bias + relu into U staging (Wb0), then row-normalize ----
    float* Us = Wb0;                   // [64][USTR], safe: Wb0 last read at tile 6
    #pragma unroll
    for (int u = 0; u < 2; ++u) {
        int col0 = n02 + 8 * u + 2 * t4;
        float2 bb = *(const float2*)&b2[col0];
        #pragma unroll
        for (int mt = 0; mt < 4; ++mt) {
            int r = mt * 16 + g;
            Us[r * USTR + col0]           = fmaxf(c2[mt][u][0] + bb.x, 0.f);
            Us[r * USTR + col0 + 1]       = fmaxf(c2[mt][u][1] + bb.y, 0.f);
            Us[(r + 8) * USTR + col0]     = fmaxf(c2[mt][u][2] + bb.x, 0.f);
            Us[(r + 8) * USTR + col0 + 1] = fmaxf(c2[mt][u][3] + bb.y, 0.f);
        }
    }
    __syncthreads();

    // Normalize: thread handles row r = tid>>2, cols q*32..q*32+31
    {
        const int r = tid >> 2, q = tid & 3;
        const float* ur = Us + r * USTR + q * 32;
        float v[32];
        float sq = 0.f;
        #pragma unroll
        for (int i = 0; i < 32; ++i) { v[i] = ur[i]; sq = fmaf(v[i], v[i], sq); }
        sq += __shfl_xor_sync(0xffffffffu, sq, 1);
        sq += __shfl_xor_sync(0xffffffffu, sq, 2);
        float inv = 1.f / fmaxf(sqrtf(sq), 1e-8f);
        float* go = gout + (size_t)(row0 + r) * D_OUT + q * 32;
        #pragma unroll
        for (int i = 0; i < 8; ++i) {
            float4 o = make_float4(v[4*i] * inv, v[4*i+1] * inv,
                                   v[4*i+2] * inv, v[4*i+3] * inv);
            *(float4*)&go[4 * i] = o;
        }
    }
}

// ---------------- Scoring on pre-normalized vectors ----------------
__global__ __launch_bounds__(256)
void score_kernel(const int* __restrict__ sw_ids, const float* __restrict__ sw_table,
                  float* __restrict__ out)
{
    int warp = (blockIdx.x * blockDim.x + threadIdx.x) >> 5;
    if (warp >= BATCH) return;
    int lane = threadIdx.x & 31;
    int gq   = lane >> 3;
    int l8   = lane & 7;

    const float* un = g_uv;
    const float* vn = g_uv + (size_t)BATCH * D_OUT;

    int col = (warp + gq) & (BATCH - 1);
    const float4* u4 = (const float4*)&un[(size_t)warp * D_OUT + l8 * 16];
    const float4* v4 = (const float4*)&vn[(size_t)col  * D_OUT + l8 * 16];

    float d = 0.f;
    #pragma unroll
    for (int i = 0; i < 4; ++i) {
        float4 a = u4[i], b = v4[i];
        d = fmaf(a.x, b.x, fmaf(a.y, b.y, fmaf(a.z, b.z, fmaf(a.w, b.w, d))));
    }
    d += __shfl_xor_sync(0xffffffffu, d, 4);
    d += __shfl_xor_sync(0xffffffffu, d, 2);
    d += __shfl_xor_sync(0xffffffffu, d, 1);

    if (l8 == 0)
        out[warp * N_NEG4 + gq] =
            d - logf(__ldg(&sw_table[__ldg(&sw_ids[col])]));
}

extern "C" void kernel_launch(void* const* d_in, const int* in_sizes, int n_in,
                              void* d_out, int out_size)
{
    const int*   user_ids    = (const int*)  d_in[0];
    const int*   item_ids    = (const int*)  d_in[1];
    const int*   sw_ids      = (const int*)  d_in[2];
    const float* user_tables = (const float*)d_in[3];
    const float* item_tables = (const float*)d_in[4];
    const float* sw_table    = (const float*)d_in[5];
    const float* uW1 = (const float*)d_in[6];
    const float* ub1 = (const float*)d_in[7];
    const float* uW2 = (const float*)d_in[8];
    const float* ub2 = (const float*)d_in[9];
    const float* iW1 = (const float*)d_in[10];
    const float* ib1 = (const float*)d_in[11];
    const float* iW2 = (const float*)d_in[12];
    const float* ib2 = (const float*)d_in[13];
    (void)in_sizes; (void)n_in; (void)out_size;

    const int smem_bytes = SMEM_FLOATS * (int)sizeof(float);   // 134,144 B
    cudaFuncSetAttribute(tower_kernel, cudaFuncAttributeMaxDynamicSharedMemorySize,
                         smem_bytes);

    tower_kernel<<<128, 256, smem_bytes>>>(user_ids, item_ids,
                                           user_tables, item_tables,
                                           uW1, ub1, uW2, ub2,
                                           iW1, ib1, iW2, ib2);
    score_kernel<<<512, 256>>>(sw_ids, sw_table, (float*)d_out);
}